// round 3
// baseline (speedup 1.0000x reference)
#include <cuda_runtime.h>
#include <math.h>

#define NIMG 24   // b*s = 4*6
#define NTASK 144 // b*s*s

// ---------------- device scratch (no allocations allowed) ----------------
__device__ float g_x [NIMG*3*64*64];
__device__ float g_f1[NIMG*32*32*32];
__device__ float g_f2[NIMG*48*16*16];
__device__ float g_f3[NIMG*64*64];    // [n][c][p], p = y*8+x
__device__ float g_u [NIMG*128*64];   // [n][k][p]  (transposed for smem loads)
__device__ float g_v [NIMG*64*128];   // [n][q][k]  (includes +bg1)
__device__ float g_P [NTASK];         // score[b][J][I]

// ---------------- pack support_x / query_x into g_x ----------------
__global__ void pack_kernel(const float* __restrict__ sx, const float* __restrict__ qx) {
    int idx = blockIdx.x * blockDim.x + threadIdx.x;
    if (idx >= NIMG * 12288) return;
    int n = idx / 12288, r = idx - n * 12288;
    int b = n / 6, s = n - b * 6;
    g_x[idx] = (s < 5) ? sx[(b * 5 + s) * 12288 + r] : qx[b * 12288 + r];
}

// ---------------- generic stride-2 SAME 3x3 conv + relu ----------------
// pad_lo = 0, pad_hi = 1 (JAX SAME for even input, stride 2, k=3)
template<int CI, int HIN>
__device__ __forceinline__ void conv_body(const float* __restrict__ in,
                                          const float* __restrict__ wt,
                                          const float* __restrict__ bias,
                                          float* __restrict__ out, int CO) {
    constexpr int WIN = HIN, HOUT = HIN / 2, WOUT = HIN / 2;
    constexpr int PH = HIN + 1, PW = WIN + 1;
    constexpr int KK = CI * 9;
    constexpr int IN_ELEMS = CI * PH * PW;
    constexpr int WOFF = (IN_ELEMS + 3) & ~3;
    extern __shared__ float sm[];
    float* in_s = sm;
    float* w_s  = sm + WOFF;   // [KK][8]

    int n = blockIdx.x;
    int co0 = blockIdx.y * 8;
    int tid = threadIdx.x;

    for (int idx = tid; idx < IN_ELEMS; idx += blockDim.x) {
        int ci = idx / (PH * PW);
        int r = idx - ci * (PH * PW);
        int y = r / PW, x = r - y * PW;
        float v = 0.f;
        if (y < HIN && x < WIN) v = in[((n * CI + ci) * HIN + y) * WIN + x];
        in_s[idx] = v;
    }
    for (int idx = tid; idx < KK * 8; idx += blockDim.x) {
        int k = idx >> 3, c8 = idx & 7;
        w_s[idx] = wt[(co0 + c8) * KK + k];
    }
    __syncthreads();

    float bv[8];
    #pragma unroll
    for (int c8 = 0; c8 < 8; c8++) bv[c8] = bias[co0 + c8];

    for (int pos = tid; pos < HOUT * WOUT; pos += blockDim.x) {
        int y = pos / WOUT, x = pos - y * WOUT;
        float acc[8];
        #pragma unroll
        for (int c8 = 0; c8 < 8; c8++) acc[c8] = bv[c8];
        for (int ci = 0; ci < CI; ci++) {
            const float* ip = in_s + (ci * PH + 2 * y) * PW + 2 * x;
            #pragma unroll
            for (int kh = 0; kh < 3; kh++) {
                #pragma unroll
                for (int kw = 0; kw < 3; kw++) {
                    float iv = ip[kh * PW + kw];
                    int k = ci * 9 + kh * 3 + kw;
                    const float4 w0 = *(const float4*)(w_s + k * 8);
                    const float4 w1 = *(const float4*)(w_s + k * 8 + 4);
                    acc[0] = fmaf(iv, w0.x, acc[0]);
                    acc[1] = fmaf(iv, w0.y, acc[1]);
                    acc[2] = fmaf(iv, w0.z, acc[2]);
                    acc[3] = fmaf(iv, w0.w, acc[3]);
                    acc[4] = fmaf(iv, w1.x, acc[4]);
                    acc[5] = fmaf(iv, w1.y, acc[5]);
                    acc[6] = fmaf(iv, w1.z, acc[6]);
                    acc[7] = fmaf(iv, w1.w, acc[7]);
                }
            }
        }
        #pragma unroll
        for (int c8 = 0; c8 < 8; c8++)
            out[((n * CO + co0 + c8) * HOUT + y) * WOUT + x] = fmaxf(acc[c8], 0.f);
    }
}

__global__ void conv1_k(const float* wt, const float* b) { conv_body<3, 64>(g_x,  wt, b, g_f1, 32); }
__global__ void conv2_k(const float* wt, const float* b) { conv_body<32, 32>(g_f1, wt, b, g_f2, 48); }
__global__ void conv3_k(const float* wt, const float* b) { conv_body<48, 16>(g_f2, wt, b, g_f3, 64); }

// ---------------- logits + cls_loss (single CTA) ----------------
__global__ void logits_kernel(const float* __restrict__ Wlog, const float* __restrict__ blog,
                              const int* __restrict__ sy, const int* __restrict__ qy,
                              float* __restrict__ out) {
    __shared__ float pooled[NIMG * 64];
    __shared__ float lg[NIMG * 64];
    __shared__ float lps[NIMG];
    int tid = threadIdx.x;
    for (int idx = tid; idx < NIMG * 64; idx += 256) {
        const float* f = g_f3 + idx * 64;
        float s = 0.f;
        #pragma unroll 4
        for (int p = 0; p < 64; p++) s += f[p];
        pooled[idx] = s * (1.f / 64.f);
    }
    __syncthreads();
    for (int idx = tid; idx < NIMG * 64; idx += 256) {
        int n = idx >> 6, cl = idx & 63;
        const float* pn = pooled + n * 64;
        float s = blog[cl];
        for (int c = 0; c < 64; c++) s = fmaf(pn[c], Wlog[c * 64 + cl], s);
        lg[idx] = s;
    }
    __syncthreads();
    if (tid < NIMG) {
        int n = tid, b = n / 6, ss = n - b * 6;
        int lab = (ss < 5) ? sy[b * 5 + ss] : qy[b];
        const float* l = lg + n * 64;
        float m = l[0];
        for (int c = 1; c < 64; c++) m = fmaxf(m, l[c]);
        float se = 0.f;
        for (int c = 0; c < 64; c++) se += expf(l[c] - m);
        lps[n] = l[lab] - m - logf(se);
    }
    __syncthreads();
    if (tid == 0) {
        float s = 0.f;
        for (int n = 0; n < NIMG; n++) s += lps[n];
        out[0] = -s / (float)NIMG;
    }
}

// ---------------- u = a@W1a, v = a@W1b + bg1 ----------------
// grid (24, 2): each CTA computes one k-half (64 of 128 k's)
__global__ void uv_kernel(const float* __restrict__ Wg1, const float* __restrict__ bg1) {
    extern __shared__ float sm[];
    float* a_s  = sm;                 // [64][68] : a[p][c], c2 = 66
    float* wa_s = sm + 64 * 68;       // [66][64]
    float* wb_s = wa_s + 66 * 64;     // [66][64]
    float* bgs  = wb_s + 66 * 64;     // [64]
    int n = blockIdx.x;
    int k0 = blockIdx.y * 64;
    int tid = threadIdx.x;

    for (int idx = tid; idx < 64 * 64; idx += 256) {
        int c = idx >> 6, p = idx & 63;
        a_s[p * 68 + c] = g_f3[(n * 64 + c) * 64 + p];
    }
    for (int idx = tid; idx < 66 * 64; idx += 256) {
        int c = idx >> 6, kk = idx & 63;
        wa_s[idx] = Wg1[c * 128 + k0 + kk];
        wb_s[idx] = Wg1[(66 + c) * 128 + k0 + kk];
    }
    if (tid < 64) {
        bgs[tid] = bg1[k0 + tid];
        int p = tid;
        a_s[p * 68 + 64] = (float)(p >> 3) * 0.125f;
        a_s[p * 68 + 65] = (float)(p & 7) * 0.125f;
    }
    __syncthreads();

    int kg = tid & 7, pgg = tid >> 3;
    int p0 = pgg * 2, kb = kg * 8;
    float ua[2][8], va[2][8];
    #pragma unroll
    for (int kk = 0; kk < 8; kk++) {
        ua[0][kk] = 0.f; ua[1][kk] = 0.f;
        va[0][kk] = bgs[kb + kk]; va[1][kk] = bgs[kb + kk];
    }
    for (int c = 0; c < 66; c++) {
        float a0 = a_s[p0 * 68 + c];
        float a1 = a_s[(p0 + 1) * 68 + c];
        float4 w0 = *(const float4*)(wa_s + c * 64 + kb);
        float4 w1 = *(const float4*)(wa_s + c * 64 + kb + 4);
        float4 x0 = *(const float4*)(wb_s + c * 64 + kb);
        float4 x1 = *(const float4*)(wb_s + c * 64 + kb + 4);
        float wv[8] = {w0.x, w0.y, w0.z, w0.w, w1.x, w1.y, w1.z, w1.w};
        float xv[8] = {x0.x, x0.y, x0.z, x0.w, x1.x, x1.y, x1.z, x1.w};
        #pragma unroll
        for (int kk = 0; kk < 8; kk++) {
            ua[0][kk] = fmaf(a0, wv[kk], ua[0][kk]);
            ua[1][kk] = fmaf(a1, wv[kk], ua[1][kk]);
            va[0][kk] = fmaf(a0, xv[kk], va[0][kk]);
            va[1][kk] = fmaf(a1, xv[kk], va[1][kk]);
        }
    }
    #pragma unroll
    for (int tp = 0; tp < 2; tp++)
        #pragma unroll
        for (int kk = 0; kk < 8; kk++) {
            int gk = k0 + kb + kk;
            g_u[(n * 128 + gk) * 64 + p0 + tp] = ua[tp][kk];
            g_v[(n * 64 + p0 + tp) * 128 + gk] = va[tp][kk];
        }
}

// ---------------- relation network core: one CTA per (b,J,I) ----------------
__global__ void __launch_bounds__(256, 1)
relnet_kernel(const float* __restrict__ Wg2, const float* __restrict__ bg2,
              const float* __restrict__ Wf1, const float* __restrict__ bf1,
              const float* __restrict__ Wf2, const float* __restrict__ bf2) {
    extern __shared__ float sm[];
    float* Us   = sm;            // [128][64]  u[ni][k][p]
    float* Vs   = sm + 8192;     // [64][128]  v[nj][q][k]
    float* Ws   = sm + 16384;    // [128][64]  Wg2[k][c]
    float* part = sm + 24576;    // [32][64]
    float* xf   = sm + 26624;    // [64]
    float* hsm  = sm + 26688;    // [16]

    int task = blockIdx.x;
    int b = task / 36, rem = task - b * 36;
    int J = rem / 6, I = rem - J * 6;
    int ni = b * 6 + I, nj = b * 6 + J;
    int tid = threadIdx.x;

    for (int idx = tid; idx < 8192; idx += 256) {
        Us[idx] = g_u[ni * 8192 + idx];
        Vs[idx] = g_v[nj * 8192 + idx];
        Ws[idx] = Wg2[idx];
    }
    __syncthreads();

    int cg = tid & 7, pg = tid >> 3;
    int c0 = cg << 3;
    float bgr[8];
    #pragma unroll
    for (int t = 0; t < 8; t++) bgr[t] = bg2[c0 + t];

    float acc8[8] = {0.f, 0.f, 0.f, 0.f, 0.f, 0.f, 0.f, 0.f};

    for (int it = 0; it < 16; ++it) {
        int pt = pg + (it << 5);          // warp-uniform q per iteration
        int q = pt >> 3;
        int p0 = (pt & 7) << 3;
        const float* vq = Vs + q * 128;
        const float* up = Us + p0;
        const float* wp = Ws + c0;

        float ct[8][8];
        #pragma unroll
        for (int tp = 0; tp < 8; tp++)
            #pragma unroll
            for (int tc = 0; tc < 8; tc++) ct[tp][tc] = 0.f;

        #pragma unroll 4
        for (int k = 0; k < 128; ++k) {
            float4 uA = *(const float4*)(up + k * 64);
            float4 uB = *(const float4*)(up + k * 64 + 4);
            float4 wA = *(const float4*)(wp + k * 64);
            float4 wB = *(const float4*)(wp + k * 64 + 4);
            float vk = vq[k];
            float h[8];
            h[0] = fmaxf(uA.x + vk, 0.f); h[1] = fmaxf(uA.y + vk, 0.f);
            h[2] = fmaxf(uA.z + vk, 0.f); h[3] = fmaxf(uA.w + vk, 0.f);
            h[4] = fmaxf(uB.x + vk, 0.f); h[5] = fmaxf(uB.y + vk, 0.f);
            h[6] = fmaxf(uB.z + vk, 0.f); h[7] = fmaxf(uB.w + vk, 0.f);
            float w[8] = {wA.x, wA.y, wA.z, wA.w, wB.x, wB.y, wB.z, wB.w};
            #pragma unroll
            for (int tp = 0; tp < 8; tp++)
                #pragma unroll
                for (int tc = 0; tc < 8; tc++)
                    ct[tp][tc] = fmaf(h[tp], w[tc], ct[tp][tc]);
        }
        #pragma unroll
        for (int tp = 0; tp < 8; tp++)
            #pragma unroll
            for (int tc = 0; tc < 8; tc++)
                acc8[tc] += fmaxf(ct[tp][tc] + bgr[tc], 0.f);
    }

    #pragma unroll
    for (int t = 0; t < 8; t++) part[pg * 64 + c0 + t] = acc8[t];
    __syncthreads();

    if (tid < 64) {
        float s = 0.f;
        for (int g = 0; g < 32; g++) s += part[g * 64 + tid];
        xf[tid] = s;
    }
    __syncthreads();
    if (tid < 16) {
        float s = bf1[tid];
        for (int c = 0; c < 64; c++) s = fmaf(xf[c], Wf1[c * 16 + tid], s);
        hsm[tid] = fmaxf(s, 0.f);
    }
    __syncthreads();
    if (tid == 0) {
        float s = bf2[0];
        for (int t = 0; t < 16; t++) s = fmaf(hsm[t], Wf2[t], s);
        g_P[task] = 1.f / (1.f + expf(-s));
    }
}

// ---------------- final losses ----------------
__global__ void loss_kernel(const int* __restrict__ sy, const int* __restrict__ qy,
                            float* __restrict__ out) {
    __shared__ float es[256];
    __shared__ float s2[4], a2[4];
    int tid = threadIdx.x;
    if (tid < 4) { s2[tid] = 0.f; a2[tid] = 0.f; }
    __syncthreads();
    float e = 0.f;
    if (tid < NTASK) {
        int b = tid / 36, r = tid - b * 36;
        int J = r / 6, I = r - J * 6;
        float p  = g_P[tid];
        float pt = g_P[b * 36 + I * 6 + J];
        int labJ = (J < 5) ? sy[b * 5 + J] : qy[b];
        int labI = (I < 5) ? sy[b * 5 + I] : qy[b];
        float y = (labJ == labI) ? 1.f : 0.f;
        e = (p - y) * (p - y);
        float symv = 0.5f * (p + pt), antiv = 0.5f * (p - pt);
        atomicAdd(&s2[b], symv * symv);
        atomicAdd(&a2[b], antiv * antiv);
    }
    es[tid] = e;
    __syncthreads();
    for (int off = 128; off > 0; off >>= 1) {
        if (tid < off) es[tid] += es[tid + off];
        __syncthreads();
    }
    if (tid == 0) {
        float euc = es[0] / (float)NTASK;
        float sl = 0.f;
        for (int bb = 0; bb < 4; bb++) {
            float sn = sqrtf(s2[bb]), an = sqrtf(a2[bb]);
            sl += (sn - an) / (sn + an);
        }
        sl *= 0.25f;
        out[2] = sl;
        out[1] = euc - 0.1f * sl;
    }
}

// ---------------- launch ----------------
extern "C" void kernel_launch(void* const* d_in, const int* in_sizes, int n_in,
                              void* d_out, int out_size) {
    const float* sx   = (const float*)d_in[0];
    const int*   sy   = (const int*)  d_in[1];
    const float* qx   = (const float*)d_in[2];
    const int*   qy   = (const int*)  d_in[3];
    const float* k1   = (const float*)d_in[4];
    const float* bc1  = (const float*)d_in[5];
    const float* k2   = (const float*)d_in[6];
    const float* bc2  = (const float*)d_in[7];
    const float* k3   = (const float*)d_in[8];
    const float* bc3  = (const float*)d_in[9];
    const float* Wlog = (const float*)d_in[10];
    const float* blog = (const float*)d_in[11];
    const float* Wg1  = (const float*)d_in[12];
    const float* bg1  = (const float*)d_in[13];
    const float* Wg2  = (const float*)d_in[14];
    const float* bg2  = (const float*)d_in[15];
    const float* Wf1  = (const float*)d_in[16];
    const float* bf1  = (const float*)d_in[17];
    const float* Wf2  = (const float*)d_in[18];
    const float* bf2  = (const float*)d_in[19];
    float* out = (float*)d_out;

    // dynamic smem sizes (bytes)
    const int smem_c1  = (((3  * 65 * 65 + 3) & ~3) + 8 * 27 ) * 4;   //  ~51.6 KB
    const int smem_c2  = (((32 * 33 * 33 + 3) & ~3) + 8 * 288) * 4;   // ~148.6 KB
    const int smem_c3  = (((48 * 17 * 17 + 3) & ~3) + 8 * 432) * 4;   //  ~69.3 KB
    const int smem_uv  = (64 * 68 + 2 * 66 * 64 + 64) * 4;            //  ~51.5 KB
    const int smem_rel = (3 * 8192 + 2048 + 64 + 16) * 4;             // ~106.8 KB

    cudaFuncSetAttribute(conv1_k,       cudaFuncAttributeMaxDynamicSharedMemorySize, smem_c1);
    cudaFuncSetAttribute(conv2_k,       cudaFuncAttributeMaxDynamicSharedMemorySize, smem_c2);
    cudaFuncSetAttribute(conv3_k,       cudaFuncAttributeMaxDynamicSharedMemorySize, smem_c3);
    cudaFuncSetAttribute(uv_kernel,     cudaFuncAttributeMaxDynamicSharedMemorySize, smem_uv);
    cudaFuncSetAttribute(relnet_kernel, cudaFuncAttributeMaxDynamicSharedMemorySize, smem_rel);

    pack_kernel<<<(NIMG * 12288 + 255) / 256, 256>>>(sx, qx);
    conv1_k<<<dim3(NIMG, 4), 256, smem_c1>>>(k1, bc1);
    conv2_k<<<dim3(NIMG, 6), 256, smem_c2>>>(k2, bc2);
    conv3_k<<<dim3(NIMG, 8), 256, smem_c3>>>(k3, bc3);
    logits_kernel<<<1, 256>>>(Wlog, blog, sy, qy, out);
    uv_kernel<<<dim3(NIMG, 2), 256, smem_uv>>>(Wg1, bg1);
    relnet_kernel<<<NTASK, 256, smem_rel>>>(Wg2, bg2, Wf1, bf1, Wf2, bf2);
    loss_kernel<<<1, 256>>>(sy, qy, out);
}